// round 6
// baseline (speedup 1.0000x reference)
#include <cuda_runtime.h>
#include <cuda_fp16.h>
#include <cstdint>

// ============================================================================
// ConditionEmbedder — sm_103 (non-'a' target!) tensor-core version.
// tcgen05 is rejected by this harness's ptxas target, so we use baseline-PTX
// mma.sync.m16n8k16 (f16 in, f32 accum) + ldmatrix, both sm_80-era features.
//
//   out[b,:] = sum_d ( drop[b,d] ? emb_w[d,:]
//                                : softmax(labels[b,d]*w1[d,:]+b1[d,:]) @ w2[d]^T )
//
// Per CTA: 128 batch rows, 8 warps x one 16-row M-tile. All 8 dims accumulate
// into the same fp32 accumulators (64 regs/thread). A-fragments (softmax rows)
// are computed straight into registers in mma fragment order — no smem, no
// LDSM on the A side. B (w2[d], fp16, [k_out][h] = col-major for mma) is staged
// in smem with a 272B padded row stride so ldmatrix is bank-conflict-free.
// ============================================================================

static constexpr int BATCH        = 131072;
static constexpr int DDIMS        = 8;
static constexpr int HDIM         = 128;
static constexpr int ROWS_PER_CTA = 128;
static constexpr int NBLOCKS      = BATCH / ROWS_PER_CTA;  // 1024
static constexpr int CTA_THREADS  = 256;                   // 8 warps

static constexpr int BROW_BYTES   = 272;                   // 256 + 16B pad (bank spread)

// smem layout (dynamic)
static constexpr int SMEM_LABELS  = 0;                     // 128*8*4  = 4096
static constexpr int SMEM_W1      = 4096;                  // 8*128*4  = 4096
static constexpr int SMEM_B1      = 8192;                  // 4096
static constexpr int SMEM_EMB     = 12288;                 // 4096
static constexpr int SMEM_BT      = 16384;                 // 128*272  = 34816
static constexpr int SMEM_TOTAL   = SMEM_BT + 128 * BROW_BYTES;  // 51200 B

// Pre-converted fp16 w2, [d][k_out][h] row-major (== col-major B for the mma).
__device__ __align__(16) __half g_w2h[DDIMS * HDIM * HDIM];

__global__ void prep_w2_kernel(const float* __restrict__ w2) {
    int i = blockIdx.x * 256 + threadIdx.x;     // exactly 131072 elements
    g_w2h[i] = __float2half(w2[i]);
}

__device__ __forceinline__ uint32_t smem_to_u32(const void* p) {
    uint32_t a;
    asm("{ .reg .u64 t; cvta.to.shared.u64 t, %1; cvt.u32.u64 %0, t; }"
        : "=r"(a) : "l"(p));
    return a;
}

__global__ void __launch_bounds__(CTA_THREADS)
cond_embed_kernel(const float* __restrict__ labels,
                  const float* __restrict__ emb_w,
                  const float* __restrict__ w1,
                  const float* __restrict__ b1,
                  const int*   __restrict__ uncond_p,
                  float*       __restrict__ out)
{
    extern __shared__ __align__(16) char smem[];
    float* lab_sm = reinterpret_cast<float*>(smem + SMEM_LABELS);
    float* w1_sm  = reinterpret_cast<float*>(smem + SMEM_W1);
    float* b1_sm  = reinterpret_cast<float*>(smem + SMEM_B1);
    float* emb_sm = reinterpret_cast<float*>(smem + SMEM_EMB);

    const int tid  = threadIdx.x;
    const int wid  = tid >> 5;
    const int lane = tid & 31;
    const int gr   = lane >> 2;     // group id (0..7)
    const int q    = lane & 3;      // thread-in-group
    const int blk  = blockIdx.x;

    // Stage labels block + small weight tables
    for (int i = tid; i < 1024; i += CTA_THREADS) {
        lab_sm[i] = labels[(size_t)blk * 1024 + i];
        w1_sm[i]  = w1[i];
        b1_sm[i]  = b1[i];
        emb_sm[i] = emb_w[i];
    }
    const int force_drop = *uncond_p;
    __syncthreads();

    // fp32 accumulators: 16 n-tiles x {c0,c1 (row gr), c2,c3 (row gr+8)}
    float acc[64];
    #pragma unroll
    for (int i = 0; i < 64; ++i) acc[i] = 0.0f;

    // A fragments for 8 k-chunks: [4t+0]=row0/k-lo, [4t+1]=row1/k-lo,
    //                             [4t+2]=row0/k-hi, [4t+3]=row1/k-hi
    uint32_t afr[32];

    unsigned mask0 = 0, mask1 = 0;          // dropped-dim bitmask per row
    const int r0 = wid * 16 + gr;           // local rows owned by this lane
    const int r1 = r0 + 8;

    const uint32_t smemB = smem_to_u32(smem) + SMEM_BT;
    // ldmatrix.x2 lane addressing: lanes 0-7 -> rows of k-lo matrix,
    // lanes 8-15 -> rows of k-hi matrix (+16B col offset)
    const uint32_t bln = smemB + (uint32_t)(lane & 7) * BROW_BYTES
                               + (uint32_t)((lane >> 3) & 1) * 16u;

    for (int d = 0; d < DDIMS; ++d) {
        __syncthreads();   // prior dim's ldmatrix reads complete before overwrite

        // ---- stage w2[d] fp16 [128 x 128] into padded smem (2048 x 16B) ----
        {
            const uint4* src = reinterpret_cast<const uint4*>(g_w2h + d * HDIM * HDIM);
            #pragma unroll
            for (int it = 0; it < 8; ++it) {
                int idx = tid + it * CTA_THREADS;          // 0..2047
                int n = idx >> 4, jj = idx & 15;
                *reinterpret_cast<uint4*>(smem + SMEM_BT + n * BROW_BYTES + jj * 16)
                    = src[idx];
            }
        }

        // ---- per-row drop detection (uniform per quad) ----
        const float x0 = lab_sm[r0 * DDIMS + d];
        const float x1 = lab_sm[r1 * DDIMS + d];
        const uint32_t xb0 = __float_as_uint(x0) & 0x7fffffffu;
        const uint32_t xb1 = __float_as_uint(x1) & 0x7fffffffu;
        const bool dr0 = (xb0 > 0x7f800000u) || force_drop;
        const bool dr1 = (xb1 > 0x7f800000u) || force_drop;
        if (dr0) mask0 |= 1u << d;
        if (dr1) mask1 |= 1u << d;
        const float xs0 = dr0 ? 0.0f : x0;
        const float xs1 = dr1 ? 0.0f : x1;

        // ---- softmax straight into A fragments (no divergence: shfl-safe) ----
        // lane's 32 cols per row: c(j) = 16*(j>>2) + 8*((j>>1)&1) + (j&1) + 2q
        #pragma unroll
        for (int rr = 0; rr < 2; ++rr) {
            const float xs = rr ? xs1 : xs0;
            const bool  dr = rr ? dr1 : dr0;
            float hv[32];
            float mx = -1e30f;
            #pragma unroll
            for (int j = 0; j < 32; ++j) {
                const int c = 16 * (j >> 2) + 8 * ((j >> 1) & 1) + (j & 1) + 2 * q;
                hv[j] = fmaf(xs, w1_sm[d * HDIM + c], b1_sm[d * HDIM + c]);
                mx = fmaxf(mx, hv[j]);
            }
            mx = fmaxf(mx, __shfl_xor_sync(0xffffffffu, mx, 1));
            mx = fmaxf(mx, __shfl_xor_sync(0xffffffffu, mx, 2));
            float z = 0.0f;
            #pragma unroll
            for (int j = 0; j < 32; ++j) {
                hv[j] = __expf(hv[j] - mx);
                z += hv[j];
            }
            z += __shfl_xor_sync(0xffffffffu, z, 1);
            z += __shfl_xor_sync(0xffffffffu, z, 2);
            const float inv = dr ? 0.0f : __fdividef(1.0f, z);  // drop -> zero frag
            #pragma unroll
            for (int t = 0; t < 8; ++t) {
                __half2 plo = __floats2half2_rn(hv[4 * t + 0] * inv,
                                                hv[4 * t + 1] * inv);
                __half2 phi = __floats2half2_rn(hv[4 * t + 2] * inv,
                                                hv[4 * t + 3] * inv);
                afr[4 * t + 0 + rr] = *reinterpret_cast<uint32_t*>(&plo);
                afr[4 * t + 2 + rr] = *reinterpret_cast<uint32_t*>(&phi);
            }
        }

        __syncthreads();   // B tile visible

        // ---- D += A @ B^T : 8 k-chunks x 16 n-tiles of m16n8k16 ----
        #pragma unroll
        for (int t = 0; t < 8; ++t) {
            #pragma unroll
            for (int nt = 0; nt < 16; ++nt) {
                const uint32_t addr = bln + (uint32_t)nt * (8u * BROW_BYTES)
                                          + (uint32_t)t * 32u;
                uint32_t bf0, bf1;
                asm volatile(
                    "ldmatrix.sync.aligned.m8n8.x2.shared.b16 {%0,%1}, [%2];"
                    : "=r"(bf0), "=r"(bf1) : "r"(addr));
                asm volatile(
                    "mma.sync.aligned.m16n8k16.row.col.f32.f16.f16.f32 "
                    "{%0,%1,%2,%3}, {%4,%5,%6,%7}, {%8,%9}, {%0,%1,%2,%3};"
                    : "+f"(acc[4 * nt + 0]), "+f"(acc[4 * nt + 1]),
                      "+f"(acc[4 * nt + 2]), "+f"(acc[4 * nt + 3])
                    : "r"(afr[4 * t + 0]), "r"(afr[4 * t + 1]),
                      "r"(afr[4 * t + 2]), "r"(afr[4 * t + 3]),
                      "r"(bf0), "r"(bf1));
            }
        }
    }

    // ---- epilogue: add emb rows for dropped dims, store float2 pairs ----
    const size_t base0 = ((size_t)blk * ROWS_PER_CTA + r0) * HDIM;
    const size_t base1 = ((size_t)blk * ROWS_PER_CTA + r1) * HDIM;
    #pragma unroll
    for (int nt = 0; nt < 16; ++nt) {
        const int c = nt * 8 + 2 * q;
        float v0 = acc[4 * nt + 0], v1 = acc[4 * nt + 1];
        float v2 = acc[4 * nt + 2], v3 = acc[4 * nt + 3];
        unsigned m = mask0;
        while (m) {
            const int dd = __ffs(m) - 1; m &= m - 1;
            v0 += emb_sm[dd * HDIM + c];
            v1 += emb_sm[dd * HDIM + c + 1];
        }
        m = mask1;
        while (m) {
            const int dd = __ffs(m) - 1; m &= m - 1;
            v2 += emb_sm[dd * HDIM + c];
            v3 += emb_sm[dd * HDIM + c + 1];
        }
        *reinterpret_cast<float2*>(out + base0 + c) = make_float2(v0, v1);
        *reinterpret_cast<float2*>(out + base1 + c) = make_float2(v2, v3);
    }
}

// ============================================================================
// kernel_launch — inputs: labels, emb_w, w1, b1, w2, train, unconditioned
//                 output: float32 [131072, 128]
// ============================================================================
extern "C" void kernel_launch(void* const* d_in, const int* in_sizes, int n_in,
                              void* d_out, int out_size)
{
    const float* labels = (const float*)d_in[0];
    const float* emb_w  = (const float*)d_in[1];
    const float* w1     = (const float*)d_in[2];
    const float* b1     = (const float*)d_in[3];
    const float* w2     = (const float*)d_in[4];
    const int*   uncond = (n_in > 6) ? (const int*)d_in[6] : (const int*)d_in[5];
    float* out = (float*)d_out;

    prep_w2_kernel<<<DDIMS * HDIM * HDIM / 256, 256>>>(w2);

    static int smem_set = 0;
    if (!smem_set) {
        cudaFuncSetAttribute(cond_embed_kernel,
                             cudaFuncAttributeMaxDynamicSharedMemorySize, SMEM_TOTAL);
        smem_set = 1;
    }
    cond_embed_kernel<<<NBLOCKS, CTA_THREADS, SMEM_TOTAL>>>(
        labels, emb_w, w1, b1, uncond, out);
}